// round 17
// baseline (speedup 1.0000x reference)
#include <cuda_runtime.h>
#include <cstdint>

#define BATCH 16
#define HEADS 12
#define DIM 64
#define FEAT 768
#define LSEQ 1025
#define MROWS (BATCH * LSEQ)   // 16400
#define EPSF 1e-8f

// Scratch (allocation-free rule: __device__ globals)
__device__ float g_q[(size_t)BATCH * HEADS * LSEQ * DIM];
__device__ float g_k[(size_t)BATCH * HEADS * LSEQ * DIM];
__device__ float g_v[(size_t)BATCH * HEADS * LSEQ * DIM];
__device__ float g_o[(size_t)MROWS * FEAT];
__device__ float g_x[(size_t)MROWS * FEAT];          // tf32-rounded X, sigma-k
__device__ float g_wt[4][(size_t)FEAT * FEAT];       // tf32-rounded W^T [n][k], sigma-k

// ---------------------------------------------------------------------------
// helpers
// ---------------------------------------------------------------------------
// sigma: within each 8-block, logical j -> pos (j<4 ? 2j : 2j-7).
// Pairs (t, t+4) land at (2t, 2t+1) => fragment loads become 8-byte vectors.
__device__ __forceinline__ int sig8(int j) {
    return (j & ~7) | ((j & 4) ? (((j & 3) << 1) | 1) : ((j & 3) << 1));
}
__device__ __forceinline__ uint32_t smem_u32(const void* p) {
    uint32_t a;
    asm("{ .reg .u64 t; cvta.to.shared.u64 t, %1; cvt.u32.u64 %0, t; }"
        : "=r"(a) : "l"(p));
    return a;
}
__device__ __forceinline__ uint32_t tf32u(float f) {
    uint32_t u;
    asm("cvt.rna.tf32.f32 %0, %1;" : "=r"(u) : "f"(f));
    return u;
}
__device__ __forceinline__ float tf32f(float f) {
    return __uint_as_float(tf32u(f));
}
__device__ __forceinline__ void mma_tf32(float* d, const uint32_t* a,
                                         uint32_t b0, uint32_t b1) {
    asm volatile("mma.sync.aligned.m16n8k8.row.col.f32.tf32.tf32.f32 "
                 "{%0,%1,%2,%3}, {%4,%5,%6,%7}, {%8,%9}, {%0,%1,%2,%3};"
                 : "+f"(d[0]), "+f"(d[1]), "+f"(d[2]), "+f"(d[3])
                 : "r"(a[0]), "r"(a[1]), "r"(a[2]), "r"(a[3]),
                   "r"(b0), "r"(b1));
}
__device__ __forceinline__ void cp16(uint32_t dst, const void* src, bool v) {
    int sz = v ? 16 : 0;
    asm volatile("cp.async.cg.shared.global [%0], [%1], 16, %2;"
                 :: "r"(dst), "l"(src), "r"(sz) : "memory");
}
#define CP_COMMIT() asm volatile("cp.async.commit_group;" ::: "memory")
#define CP_WAIT1()  asm volatile("cp.async.wait_group 1;" ::: "memory")
#define CP_WAIT0()  asm volatile("cp.async.wait_group 0;" ::: "memory")

// ---------------------------------------------------------------------------
// prepasses
// ---------------------------------------------------------------------------
// X -> tf32-rounded, sigma-permuted k (interleave lo/hi halves of each 8-block)
__global__ void xconv(const float* __restrict__ X, float* __restrict__ XO) {
    const size_t i = (size_t)blockIdx.x * 256 + threadIdx.x;   // 8-float block idx
    const float4* src = (const float4*)(X + i * 8);
    float4 a = src[0], b = src[1];
    float2* dst = (float2*)(XO + i * 8);
    dst[0] = make_float2(tf32f(a.x), tf32f(b.x));
    dst[1] = make_float2(tf32f(a.y), tf32f(b.y));
    dst[2] = make_float2(tf32f(a.z), tf32f(b.z));
    dst[3] = make_float2(tf32f(a.w), tf32f(b.w));
}
// W[k][n] -> WT[n][k] tf32-rounded, sigma-permuted k
__global__ void wtrans(const float* __restrict__ W, float* __restrict__ WT) {
    __shared__ float t[32][33];
    const int k0 = blockIdx.x * 32, n0 = blockIdx.y * 32;
    const int x = threadIdx.x, y = threadIdx.y;    // 32 x 8
#pragma unroll
    for (int i = y; i < 32; i += 8)
        t[i][x] = W[(size_t)(k0 + i) * FEAT + n0 + x];
    __syncthreads();
    const int xp = sig8(x);
#pragma unroll
    for (int i = y; i < 32; i += 8)
        WT[(size_t)(n0 + i) * FEAT + k0 + xp] = tf32f(t[x][i]);
}

// ---------------------------------------------------------------------------
// Pipelined tf32 GEMM core (CTA 128x128, BK=32, cp.async double-buffered).
// smem data sigma-permuted in k => frag loads are uint2.
// ---------------------------------------------------------------------------
#define TG_BUF 9216               // floats per buffer (A 4608 + B 4608)
#define TG_SMEM (2 * TG_BUF * 4)  // 73728 bytes

// Fused QKV: C = X * [WqT;WkT;WvT]^T, N = 2304. Epilogue per matrix.
// Q/K written sigma-permuted in d (for attention frag loads); V logical.
__global__ __launch_bounds__(256, 2) void tgemm_qkv(
    const float* __restrict__ A, const float* __restrict__ WT,
    const float* __restrict__ bq, const float* __restrict__ bk,
    const float* __restrict__ bv,
    float* __restrict__ Q, float* __restrict__ K, float* __restrict__ V)
{
    extern __shared__ uint32_t smg[];
    const int tid = threadIdx.x;
    const int wid = tid >> 5, lane = tid & 31;
    const int g = lane >> 2, tq = lane & 3;
    const int m0 = blockIdx.x * 128, n0 = blockIdx.y * 128;
    const int mw = (wid >> 1) * 32, nw = (wid & 1) * 64;

    const int mat = n0 / FEAT;                  // 0=q,1=k,2=v (CTA-uniform)
    const float* bias = (mat == 0) ? bq : (mat == 1) ? bk : bv;
    float* C = (mat == 0) ? Q : (mat == 1) ? K : V;
    const int nbase = n0 - mat * FEAT;

    const uint32_t sbase = smem_u32(smg);
    const int ar = tid >> 1, half = (tid & 1) * 16;
    const bool aval = (m0 + ar) < MROWS;
    const float* asrc = A + (size_t)(m0 + ar) * FEAT + half;
    const float* bsrc = WT + (size_t)(n0 + ar) * FEAT + half;
    const uint32_t soffA = (uint32_t)(ar * 36 + half) * 4;
    const uint32_t soffB = soffA + 4608u * 4;

    float acc[2][8][4];
#pragma unroll
    for (int i = 0; i < 2; i++)
#pragma unroll
        for (int j = 0; j < 8; j++)
#pragma unroll
            for (int q = 0; q < 4; q++) acc[i][j][q] = 0.f;

    {
#pragma unroll
        for (int j = 0; j < 4; j++) {
            cp16(sbase + soffA + 16u * j, asrc + 4 * j, aval);
            cp16(sbase + soffB + 16u * j, bsrc + 4 * j, true);
        }
        CP_COMMIT();
    }

#pragma unroll 1
    for (int s = 0; s < 24; s++) {
        const uint32_t bufo = (uint32_t)(s & 1) * TG_BUF;
        if (s + 1 < 24) {
            const uint32_t nbo = (uint32_t)((s + 1) & 1) * TG_BUF * 4;
            const int k0 = (s + 1) * 32;
#pragma unroll
            for (int j = 0; j < 4; j++) {
                cp16(sbase + nbo + soffA + 16u * j, asrc + k0 + 4 * j, aval);
                cp16(sbase + nbo + soffB + 16u * j, bsrc + k0 + 4 * j, true);
            }
            CP_COMMIT();
            CP_WAIT1();
        } else {
            CP_WAIT0();
        }
        __syncthreads();

        const uint32_t* smA = smg + bufo;
        const uint32_t* smB = smg + bufo + 4608;
#pragma unroll
        for (int ks = 0; ks < 4; ks++) {
            const int kd = ks * 8 + 2 * tq;
            uint32_t a[2][4];
#pragma unroll
            for (int mf = 0; mf < 2; mf++) {
                const int base = (mw + mf * 16 + g) * 36 + kd;
                const uint2 u0 = *(const uint2*)&smA[base];
                const uint2 u1 = *(const uint2*)&smA[base + 8 * 36];
                a[mf][0] = u0.x; a[mf][2] = u0.y;
                a[mf][1] = u1.x; a[mf][3] = u1.y;
            }
#pragma unroll
            for (int nf = 0; nf < 8; nf++) {
                const uint2 bu = *(const uint2*)&smB[(nw + nf * 8 + g) * 36 + kd];
                mma_tf32(acc[0][nf], a[0], bu.x, bu.y);
                mma_tf32(acc[1][nf], a[1], bu.x, bu.y);
            }
        }
        __syncthreads();
    }

#pragma unroll
    for (int mf = 0; mf < 2; mf++) {
#pragma unroll
        for (int hf = 0; hf < 2; hf++) {
            const int r = m0 + mw + mf * 16 + g + hf * 8;
            if (r >= MROWS) continue;
            const int bb2 = r / LSEQ, l = r - bb2 * LSEQ;
#pragma unroll
            for (int nf = 0; nf < 8; nf++) {
                const int c = nbase + nw + nf * 8 + tq * 2;
                float v0 = acc[mf][nf][hf * 2 + 0] + bias[c];
                float v1 = acc[mf][nf][hf * 2 + 1] + bias[c + 1];
                const int h = c >> 6, d = c & 63;
                float* dst = &C[(((size_t)(bb2 * HEADS + h)) * LSEQ + l) * DIM];
                if (mat == 0) {
                    dst[sig8(d)]     = tf32f(fmaxf(v0 * 0.125f, 0.f) + EPSF);
                    dst[sig8(d + 1)] = tf32f(fmaxf(v1 * 0.125f, 0.f) + EPSF);
                } else if (mat == 1) {
                    dst[sig8(d)]     = tf32f(fmaxf(v0, 0.f) + EPSF);
                    dst[sig8(d + 1)] = tf32f(fmaxf(v1, 0.f) + EPSF);
                } else {
                    *(float2*)&dst[d] = make_float2(tf32f(v0), tf32f(v1));
                }
            }
        }
    }
}

// Output GEMM: out = O * WoT^T + bo, row-major [M,768]. A (g_o) is sigma-k.
__global__ __launch_bounds__(256, 2) void tgemm_out(
    const float* __restrict__ A, const float* __restrict__ WT,
    const float* __restrict__ bias, float* __restrict__ C)
{
    extern __shared__ uint32_t smg[];
    const int tid = threadIdx.x;
    const int wid = tid >> 5, lane = tid & 31;
    const int g = lane >> 2, tq = lane & 3;
    const int m0 = blockIdx.x * 128, n0 = blockIdx.y * 128;
    const int mw = (wid >> 1) * 32, nw = (wid & 1) * 64;

    const uint32_t sbase = smem_u32(smg);
    const int ar = tid >> 1, half = (tid & 1) * 16;
    const bool aval = (m0 + ar) < MROWS;
    const float* asrc = A + (size_t)(m0 + ar) * FEAT + half;
    const float* bsrc = WT + (size_t)(n0 + ar) * FEAT + half;
    const uint32_t soffA = (uint32_t)(ar * 36 + half) * 4;
    const uint32_t soffB = soffA + 4608u * 4;

    float acc[2][8][4];
#pragma unroll
    for (int i = 0; i < 2; i++)
#pragma unroll
        for (int j = 0; j < 8; j++)
#pragma unroll
            for (int q = 0; q < 4; q++) acc[i][j][q] = 0.f;

    {
#pragma unroll
        for (int j = 0; j < 4; j++) {
            cp16(sbase + soffA + 16u * j, asrc + 4 * j, aval);
            cp16(sbase + soffB + 16u * j, bsrc + 4 * j, true);
        }
        CP_COMMIT();
    }

#pragma unroll 1
    for (int s = 0; s < 24; s++) {
        const uint32_t bufo = (uint32_t)(s & 1) * TG_BUF;
        if (s + 1 < 24) {
            const uint32_t nbo = (uint32_t)((s + 1) & 1) * TG_BUF * 4;
            const int k0 = (s + 1) * 32;
#pragma unroll
            for (int j = 0; j < 4; j++) {
                cp16(sbase + nbo + soffA + 16u * j, asrc + k0 + 4 * j, aval);
                cp16(sbase + nbo + soffB + 16u * j, bsrc + k0 + 4 * j, true);
            }
            CP_COMMIT();
            CP_WAIT1();
        } else {
            CP_WAIT0();
        }
        __syncthreads();

        const uint32_t* smA = smg + bufo;
        const uint32_t* smB = smg + bufo + 4608;
#pragma unroll
        for (int ks = 0; ks < 4; ks++) {
            const int kd = ks * 8 + 2 * tq;
            uint32_t a[2][4];
#pragma unroll
            for (int mf = 0; mf < 2; mf++) {
                const int base = (mw + mf * 16 + g) * 36 + kd;
                const uint2 u0 = *(const uint2*)&smA[base];
                const uint2 u1 = *(const uint2*)&smA[base + 8 * 36];
                a[mf][0] = u0.x; a[mf][2] = u0.y;
                a[mf][1] = u1.x; a[mf][3] = u1.y;
            }
#pragma unroll
            for (int nf = 0; nf < 8; nf++) {
                const uint2 bu = *(const uint2*)&smB[(nw + nf * 8 + g) * 36 + kd];
                mma_tf32(acc[0][nf], a[0], bu.x, bu.y);
                mma_tf32(acc[1][nf], a[1], bu.x, bu.y);
            }
        }
        __syncthreads();
    }

#pragma unroll
    for (int mf = 0; mf < 2; mf++) {
#pragma unroll
        for (int hf = 0; hf < 2; hf++) {
            const int r = m0 + mw + mf * 16 + g + hf * 8;
            if (r >= MROWS) continue;
#pragma unroll
            for (int nf = 0; nf < 8; nf++) {
                const int c = n0 + nw + nf * 8 + tq * 2;
                float v0 = acc[mf][nf][hf * 2 + 0] + bias[c];
                float v1 = acc[mf][nf][hf * 2 + 1] + bias[c + 1];
                *(float2*)&C[(size_t)r * FEAT + c] = make_float2(v0, v1);
            }
        }
    }
}

// ---------------------------------------------------------------------------
// Fused attention (q,k in [1,1024]): 8x8 full tiles, unconditional mask.
// Q/K stored sigma-d => frag loads uint2. Vt token-permuted (stride 132).
// CLS column added as scalar epilogue; CLS row via cls_row kernel.
// smem floats: |tp|[4096] | Ks[128][68] | Vt[64][132]
// ---------------------------------------------------------------------------
#define KS_OFF 4096
#define VT_OFF (KS_OFF + 128 * 68)
#define ATT_SMEM ((VT_OFF + 64 * 132) * 4)   // 84992 B

__global__ __launch_bounds__(256, 2) void attn_tf32(const float* __restrict__ tpar,
                                                    float* __restrict__ outp)
{
    extern __shared__ float sma[];
    float* tp = sma;
    uint32_t* Ks = (uint32_t*)(sma + KS_OFF);
    uint32_t* Vt = (uint32_t*)(sma + VT_OFF);

    const int tid = threadIdx.x;
    const int wid = tid >> 5, lane = tid & 31;
    const int g = lane >> 2, tq = lane & 3;
    const int q0 = 1 + blockIdx.x * 128;
    const int h = blockIdx.y;
    const int b = blockIdx.z;

    const float* qp = g_q + ((size_t)(b * HEADS + h)) * LSEQ * DIM;
    const float* kp = g_k + ((size_t)(b * HEADS + h)) * LSEQ * DIM;
    const float* vp = g_v + ((size_t)(b * HEADS + h)) * LSEQ * DIM;

    for (int i = tid; i < 4096; i += 256) tp[i] = fabsf(tpar[h * 4096 + i]);

    // ---- stage Q into Ks, extract frags (sigma layout: pairs contiguous) ----
#pragma unroll
    for (int i = 0; i < 8; i++) {
        const int idx = i * 256 + tid;
        const int r = idx >> 4, c4 = (idx & 15) << 2;
        *(uint4*)&Ks[r * 68 + c4] = *(const uint4*)&qp[(size_t)(q0 + r) * DIM + c4];
    }
    __syncthreads();

    const int rowlo = wid * 16 + g;
    uint32_t qf[8][4];
#pragma unroll
    for (int ks = 0; ks < 8; ks++) {
        const int base = rowlo * 68 + ks * 8 + 2 * tq;
        const uint2 u0 = *(const uint2*)&Ks[base];
        const uint2 u1 = *(const uint2*)&Ks[base + 8 * 68];
        qf[ks][0] = u0.x; qf[ks][2] = u0.y;
        qf[ks][1] = u1.x; qf[ks][3] = u1.y;
    }

    const int qg_lo = q0 + rowlo, qg_hi = qg_lo + 8;
    const int qq_lo = qg_lo - 1, qq_hi = qg_hi - 1;
    const int qi_lo = qq_lo >> 5, qj_lo = qq_lo & 31;
    const int qi_hi = qq_hi >> 5, qj_hi = qq_hi & 31;

    float acc_o[8][4];
#pragma unroll
    for (int j = 0; j < 8; j++)
#pragma unroll
        for (int q = 0; q < 4; q++) acc_o[j][q] = 0.f;
    float rs0 = 0.f, rs1 = 0.f;

    const uint32_t ks_base = smem_u32(Ks);

#pragma unroll 1
    for (int kt = 0; kt < 8; kt++) {
        const int ktb = kt * 128;
        __syncthreads();

        // ---- K via cp.async (rows verbatim; sigma already applied in global) ----
#pragma unroll
        for (int i = 0; i < 8; i++) {
            const int idx = i * 256 + tid;
            const int r = idx >> 4, c4 = (idx & 15) << 2;
            cp16(ks_base + (uint32_t)(r * 68 + c4) * 4,
                 kp + (size_t)(1 + ktb + r) * DIM + c4, true);
        }
        CP_COMMIT();

        // ---- V -> Vt transposed, token-permuted within 8-blocks ----
#pragma unroll
        for (int i = 0; i < 8; i++) {
            const int idx = i * 256 + tid;
            const int r = idx >> 4, c4 = (idx & 15) << 2;
            const int rp = sig8(r);
            uint4 vv = *(const uint4*)&vp[(size_t)(1 + ktb + r) * DIM + c4];
            Vt[(c4 + 0) * 132 + rp] = vv.x;
            Vt[(c4 + 1) * 132 + rp] = vv.y;
            Vt[(c4 + 2) * 132 + rp] = vv.z;
            Vt[(c4 + 3) * 132 + rp] = vv.w;
        }
        CP_WAIT0();
        __syncthreads();

        // ---- two 64-col halves: S -> mask -> P -> PV ----
#pragma unroll
        for (int hk = 0; hk < 2; hk++) {
            const int kb = hk * 64;

            float s_acc[8][4];
#pragma unroll
            for (int j = 0; j < 8; j++)
#pragma unroll
                for (int q = 0; q < 4; q++) s_acc[j][q] = 0.f;
#pragma unroll
            for (int ks = 0; ks < 8; ks++) {
                const int kd = ks * 8 + 2 * tq;
#pragma unroll
                for (int nf = 0; nf < 8; nf++) {
                    const uint2 bu = *(const uint2*)&Ks[(kb + nf * 8 + g) * 68 + kd];
                    mma_tf32(s_acc[nf], qf[ks], bu.x, bu.y);
                }
            }

            // unconditional mask (|tp| pre-staged) + eps + rowsum -> P
            uint32_t p[8][4];
#pragma unroll
            for (int nf = 0; nf < 8; nf++) {
                const int kl0 = kb + nf * 8 + 2 * tq;
#pragma unroll
                for (int e = 0; e < 2; e++) {
                    const int kk = ktb + kl0 + e;
                    const int kki = kk >> 5, kkj = kk & 31;
                    const float tlo = tp[(qi_lo - kki + 32) * 64 + (qj_lo - kkj + 32)];
                    const float thi = tp[(qi_hi - kki + 32) * 64 + (qj_hi - kkj + 32)];
                    const float vlo = fmaf(s_acc[nf][e], tlo, EPSF);
                    const float vhi = fmaf(s_acc[nf][2 + e], thi, EPSF);
                    rs0 += vlo;
                    rs1 += vhi;
                    p[nf][e] = tf32u(vlo);
                    p[nf][2 + e] = tf32u(vhi);
                }
            }

            // PV: shuffle P into A-frags; Vt frags are uint2 (token-permuted)
            const int lbase = lane & 28;
            const int slo = lbase | (tq >> 1);
            const int shi = slo + 2;
            const bool odd = (tq & 1);
#pragma unroll
            for (int s = 0; s < 8; s++) {
                uint32_t a[4];
                uint32_t e0 = __shfl_sync(0xffffffffu, p[s][0], slo);
                uint32_t e1 = __shfl_sync(0xffffffffu, p[s][1], slo);
                a[0] = odd ? e1 : e0;
                e0 = __shfl_sync(0xffffffffu, p[s][0], shi);
                e1 = __shfl_sync(0xffffffffu, p[s][1], shi);
                a[2] = odd ? e1 : e0;
                e0 = __shfl_sync(0xffffffffu, p[s][2], slo);
                e1 = __shfl_sync(0xffffffffu, p[s][3], slo);
                a[1] = odd ? e1 : e0;
                e0 = __shfl_sync(0xffffffffu, p[s][2], shi);
                e1 = __shfl_sync(0xffffffffu, p[s][3], shi);
                a[3] = odd ? e1 : e0;
#pragma unroll
                for (int nf = 0; nf < 8; nf++) {
                    const uint2 bu = *(const uint2*)&Vt[(nf * 8 + g) * 132 + kb + s * 8 + 2 * tq];
                    mma_tf32(acc_o[nf], a, bu.x, bu.y);
                }
            }
        }
    }

    // ---- rowsum reduce within quads ----
    rs0 += __shfl_xor_sync(0xffffffffu, rs0, 1);
    rs0 += __shfl_xor_sync(0xffffffffu, rs0, 2);
    rs1 += __shfl_xor_sync(0xffffffffu, rs1, 1);
    rs1 += __shfl_xor_sync(0xffffffffu, rs1, 2);

    // ---- CLS column (k=0, tm=1): q.k dot permutation-invariant ----
    {
        float d_lo = 0.f, d_hi = 0.f;
        const float* qlo = qp + (size_t)qg_lo * DIM + tq * 16;
        const float* qhi = qp + (size_t)qg_hi * DIM + tq * 16;
        const float* k0 = kp + tq * 16;
#pragma unroll
        for (int i = 0; i < 4; i++) {
            float4 kv = *(const float4*)&k0[i * 4];
            float4 ql = *(const float4*)&qlo[i * 4];
            float4 qh = *(const float4*)&qhi[i * 4];
            d_lo += ql.x * kv.x + ql.y * kv.y + ql.z * kv.z + ql.w * kv.w;
            d_hi += qh.x * kv.x + qh.y * kv.y + qh.z * kv.z + qh.w * kv.w;
        }
        d_lo += __shfl_xor_sync(0xffffffffu, d_lo, 1);
        d_lo += __shfl_xor_sync(0xffffffffu, d_lo, 2);
        d_hi += __shfl_xor_sync(0xffffffffu, d_hi, 1);
        d_hi += __shfl_xor_sync(0xffffffffu, d_hi, 2);
        const float p0_lo = d_lo + EPSF, p0_hi = d_hi + EPSF;
        rs0 += p0_lo;
        rs1 += p0_hi;
#pragma unroll
        for (int nf = 0; nf < 8; nf++) {
            const int d0 = nf * 8 + 2 * tq;      // logical d (g_v logical)
            float2 v0 = *(const float2*)&vp[d0];
            acc_o[nf][0] += p0_lo * v0.x;
            acc_o[nf][1] += p0_lo * v0.y;
            acc_o[nf][2] += p0_hi * v0.x;
            acc_o[nf][3] += p0_hi * v0.y;
        }
    }

    // ---- normalize + write sigma-d (for the sigma-k WO GEMM) ----
    {
        const float inv = 1.f / rs0;
        float* dst = outp + (size_t)(b * LSEQ + qg_lo) * FEAT + h * 64;
#pragma unroll
        for (int nf = 0; nf < 8; nf++) {
            const int d0 = nf * 8 + 2 * tq;
            dst[sig8(d0)]     = tf32f(acc_o[nf][0] * inv);
            dst[sig8(d0 + 1)] = tf32f(acc_o[nf][1] * inv);
        }
    }
    {
        const float inv = 1.f / rs1;
        float* dst = outp + (size_t)(b * LSEQ + qg_hi) * FEAT + h * 64;
#pragma unroll
        for (int nf = 0; nf < 8; nf++) {
            const int d0 = nf * 8 + 2 * tq;
            dst[sig8(d0)]     = tf32f(acc_o[nf][2] * inv);
            dst[sig8(d0 + 1)] = tf32f(acc_o[nf][3] * inv);
        }
    }
}

// ---------------------------------------------------------------------------
// CLS row (q=0): tm = 1 everywhere. q/k sigma-permuted identically (dot ok);
// v logical; output stored sigma-d.
// ---------------------------------------------------------------------------
__global__ __launch_bounds__(256) void cls_row(float* __restrict__ outp)
{
    __shared__ float q0s[64];
    __shared__ float ps[LSEQ];
    __shared__ float red[256];

    const int b = blockIdx.x, h = blockIdx.y;
    const int tid = threadIdx.x;
    const float* qp = g_q + ((size_t)(b * HEADS + h)) * LSEQ * DIM;
    const float* kp = g_k + ((size_t)(b * HEADS + h)) * LSEQ * DIM;
    const float* vp = g_v + ((size_t)(b * HEADS + h)) * LSEQ * DIM;

    if (tid < 64) q0s[tid] = qp[tid];
    __syncthreads();

    float lsum = 0.f;
    for (int k = tid; k < LSEQ; k += 256) {
        const float4* kr = (const float4*)&kp[(size_t)k * DIM];
        float dot = 0.f;
#pragma unroll
        for (int i = 0; i < 16; i++) {
            float4 kv = kr[i];
            const float* qq = &q0s[i * 4];
            dot += qq[0] * kv.x + qq[1] * kv.y + qq[2] * kv.z + qq[3] * kv.w;
        }
        const float p = dot + EPSF;
        ps[k] = p;
        lsum += p;
    }
    red[tid] = lsum;
    __syncthreads();
    for (int s = 128; s > 0; s >>= 1) {
        if (tid < s) red[tid] += red[tid + s];
        __syncthreads();
    }
    const float inv = 1.f / red[0];
    __syncthreads();

    const int d = tid & 63, ch = tid >> 6;
    float acc = 0.f;
    for (int k = ch; k < LSEQ; k += 4)
        acc += ps[k] * vp[(size_t)k * DIM + d];
    red[tid] = acc;
    __syncthreads();
    if (tid < 64) {
        const float o = (red[tid] + red[64 + tid] + red[128 + tid] + red[192 + tid]) * inv;
        outp[(size_t)(b * LSEQ) * FEAT + h * 64 + sig8(tid)] = tf32f(o);
    }
}

// ---------------------------------------------------------------------------
extern "C" void kernel_launch(void* const* d_in, const int* in_sizes, int n_in,
                              void* d_out, int out_size)
{
    const float* x    = (const float*)d_in[0];
    const float* wq   = (const float*)d_in[1];
    const float* bq   = (const float*)d_in[2];
    const float* wk   = (const float*)d_in[3];
    const float* bk   = (const float*)d_in[4];
    const float* wv   = (const float*)d_in[5];
    const float* bv   = (const float*)d_in[6];
    const float* wo   = (const float*)d_in[7];
    const float* bo   = (const float*)d_in[8];
    const float* tpar = (const float*)d_in[9];
    float* out = (float*)d_out;

    float *qp, *kp, *vp, *op, *xp, *wtp;
    cudaGetSymbolAddress((void**)&qp, g_q);
    cudaGetSymbolAddress((void**)&kp, g_k);
    cudaGetSymbolAddress((void**)&vp, g_v);
    cudaGetSymbolAddress((void**)&op, g_o);
    cudaGetSymbolAddress((void**)&xp, g_x);
    cudaGetSymbolAddress((void**)&wtp, g_wt);

    // prepasses: sigma-k tf32 X; sigma-k transposed weights (qkv packed)
    xconv<<<(MROWS * FEAT) / (8 * 256), 256>>>(x, xp);
    dim3 wg(FEAT / 32, FEAT / 32), wb(32, 8);
    wtrans<<<wg, wb>>>(wq, wtp + 0 * (size_t)FEAT * FEAT);
    wtrans<<<wg, wb>>>(wk, wtp + 1 * (size_t)FEAT * FEAT);
    wtrans<<<wg, wb>>>(wv, wtp + 2 * (size_t)FEAT * FEAT);
    wtrans<<<wg, wb>>>(wo, wtp + 3 * (size_t)FEAT * FEAT);

    cudaFuncSetAttribute(tgemm_qkv, cudaFuncAttributeMaxDynamicSharedMemorySize, TG_SMEM);
    cudaFuncSetAttribute(tgemm_out, cudaFuncAttributeMaxDynamicSharedMemorySize, TG_SMEM);

    tgemm_qkv<<<dim3((MROWS + 127) / 128, 3 * FEAT / 128), 256, TG_SMEM>>>(
        xp, wtp, bq, bk, bv, qp, kp, vp);

    cudaFuncSetAttribute(attn_tf32, cudaFuncAttributeMaxDynamicSharedMemorySize,
                         ATT_SMEM);
    attn_tf32<<<dim3(8, HEADS, BATCH), 256, ATT_SMEM>>>(tpar, op);
    cls_row<<<dim3(BATCH, HEADS), 256>>>(op);

    tgemm_out<<<dim3((MROWS + 127) / 128, FEAT / 128), 256, TG_SMEM>>>(
        op, wtp + 3 * (size_t)FEAT * FEAT, bo, out);
}